// round 1
// baseline (speedup 1.0000x reference)
#include <cuda_runtime.h>
#include <cstdint>

// Problem constants (from reference)
#define NN 50000
#define EE 800000
#define BB 4
#define CC 64
#define NROWS (BB*NN)          // 200000 rows of 64 features

// ---------------- scratch (device globals: sanctioned scratch mechanism) ----
__device__ int   g_deg[NN];
__device__ float g_norm[NN];
__device__ int   g_rowptr[NN + 1];
__device__ int   g_fill[NN];
__device__ int   g_esrc[EE];
__device__ float g_ew[EE];
__device__ float g_y1[(size_t)NROWS * CC];
__device__ float g_y2[(size_t)NROWS * CC];

// ---------------- packed f32x2 helpers ----------------
__device__ __forceinline__ unsigned long long pk2(float f) {
    unsigned long long r; unsigned u = __float_as_uint(f);
    asm("mov.b64 %0, {%1, %1};" : "=l"(r) : "r"(u));
    return r;
}
__device__ __forceinline__ unsigned long long fma2(unsigned long long a,
                                                   unsigned long long b,
                                                   unsigned long long c) {
    unsigned long long d;
    asm("fma.rn.f32x2 %0, %1, %2, %3;" : "=l"(d) : "l"(a), "l"(b), "l"(c));
    return d;
}
__device__ __forceinline__ void unpk2(unsigned long long v, float& lo, float& hi) {
    unsigned a, b;
    asm("mov.b64 {%0, %1}, %2;" : "=r"(a), "=r"(b) : "l"(v));
    lo = __uint_as_float(a); hi = __uint_as_float(b);
}

// ---------------- graph prep kernels ----------------
__global__ void k_zero_deg() {
    int i = blockIdx.x * blockDim.x + threadIdx.x;
    if (i < NN) g_deg[i] = 0;
}

__global__ void k_degree(const int* __restrict__ dst) {
    int e = blockIdx.x * blockDim.x + threadIdx.x;
    if (e < EE) atomicAdd(&g_deg[dst[e]], 1);
}

__global__ void k_norm() {
    int i = blockIdx.x * blockDim.x + threadIdx.x;
    if (i < NN) {
        int d = g_deg[i];
        g_norm[i] = rsqrtf((float)(d < 1 ? 1 : d));
    }
}

// single-block exclusive prefix sum of g_deg -> g_rowptr, g_fill
__global__ void k_scan() {
    __shared__ int sh[1024];
    const int t = threadIdx.x;
    const int CH = (NN + 1023) / 1024;   // 49
    const int base = t * CH;
    int s = 0;
    for (int i = 0; i < CH; i++) {
        int idx = base + i;
        if (idx < NN) s += g_deg[idx];
    }
    sh[t] = s;
    __syncthreads();
    for (int off = 1; off < 1024; off <<= 1) {
        int v = (t >= off) ? sh[t - off] : 0;
        __syncthreads();
        sh[t] += v;
        __syncthreads();
    }
    int run = (t == 0) ? 0 : sh[t - 1];
    for (int i = 0; i < CH; i++) {
        int idx = base + i;
        if (idx < NN) {
            g_rowptr[idx] = run;
            g_fill[idx]   = run;
            run += g_deg[idx];
        }
    }
    if (t == 1023) g_rowptr[NN] = sh[1023];
}

__global__ void k_fill(const int* __restrict__ src, const int* __restrict__ dst) {
    int e = blockIdx.x * blockDim.x + threadIdx.x;
    if (e < EE) {
        int d = dst[e];
        int s = src[e];
        int p = atomicAdd(&g_fill[d], 1);
        g_esrc[p] = s;
        g_ew[p]   = g_norm[s] * g_norm[d];
    }
}

// ---------------- SPMM: out = alpha * (A_hat @ in) + beta * add ----------------
// one warp per dst node, all 4 batches; lane covers a (batch-pair, chan-quad)
__global__ void k_spmm(const float* __restrict__ in, const float* __restrict__ addv,
                       float* __restrict__ out, float alpha, float beta) {
    const int warp = (blockIdx.x * blockDim.x + threadIdx.x) >> 5;
    if (warp >= NN) return;
    const int node = warp;
    const int lane = threadIdx.x & 31;
    const int bhalf = lane >> 4;             // 0 or 1
    const int c4 = (lane & 15) * 4;          // channel quad base

    float4 acc0 = make_float4(0.f, 0.f, 0.f, 0.f);   // batch bhalf
    float4 acc1 = make_float4(0.f, 0.f, 0.f, 0.f);   // batch bhalf+2

    const int s0 = g_rowptr[node];
    const int s1 = g_rowptr[node + 1];
    const size_t rowA = (size_t)(bhalf       * NN) * CC + c4;
    const size_t rowB = (size_t)((bhalf + 2) * NN) * CC + c4;

    for (int e = s0; e < s1; e++) {
        const int s = g_esrc[e];
        const float w = g_ew[e];
        const size_t boff = (size_t)s * CC;
        float4 v0 = *(const float4*)(in + rowA + boff);
        float4 v1 = *(const float4*)(in + rowB + boff);
        acc0.x += w * v0.x; acc0.y += w * v0.y; acc0.z += w * v0.z; acc0.w += w * v0.w;
        acc1.x += w * v1.x; acc1.y += w * v1.y; acc1.z += w * v1.z; acc1.w += w * v1.w;
    }

    const size_t noff = (size_t)node * CC;
    float4 o0, o1;
    o0.x = alpha * acc0.x; o0.y = alpha * acc0.y; o0.z = alpha * acc0.z; o0.w = alpha * acc0.w;
    o1.x = alpha * acc1.x; o1.y = alpha * acc1.y; o1.z = alpha * acc1.z; o1.w = alpha * acc1.w;
    if (beta != 0.f) {
        float4 a0 = *(const float4*)(addv + rowA + noff);
        float4 a1 = *(const float4*)(addv + rowB + noff);
        o0.x += beta * a0.x; o0.y += beta * a0.y; o0.z += beta * a0.z; o0.w += beta * a0.w;
        o1.x += beta * a1.x; o1.y += beta * a1.y; o1.z += beta * a1.z; o1.w += beta * a1.w;
    }
    *(float4*)(out + rowA + noff) = o0;
    *(float4*)(out + rowB + noff) = o1;
}

// ---------------- fused dense: out = relu([x|y1|y2] Wc + bc) Wl + bl ----------
// tile: 128 rows x 64 cols, 256 threads, thread = 8 rows x 4 cols (f32x2 pairs)
#define TR 128
#define KC 192
#define PITCH 132     // floats per k-row of Us (16B aligned stride: 528B)

__global__ void __launch_bounds__(256, 1)
k_fused(const float* __restrict__ x,
        const float* __restrict__ Wc, const float* __restrict__ bc,
        const float* __restrict__ Wl, const float* __restrict__ bl,
        float* __restrict__ out) {
    extern __shared__ float sm[];
    float* Us  = sm;                    // [KC][PITCH], reused as Hs [64][PITCH]
    float* Wcs = sm + KC * PITCH;       // [192][64]
    float* Wls = Wcs + KC * CC;         // [64][64]
    float* bcs = Wls + CC * CC;         // [64]
    float* bls = bcs + CC;              // [64]

    const int t = threadIdx.x;
    const int rowbase = blockIdx.x * TR;
    const int nrows = min(TR, NROWS - rowbase);

    // stage weights
    for (int i = t; i < (KC * CC) / 4; i += 256)
        ((float4*)Wcs)[i] = ((const float4*)Wc)[i];
    for (int i = t; i < (CC * CC) / 4; i += 256)
        ((float4*)Wls)[i] = ((const float4*)Wl)[i];
    if (t < CC) { bcs[t] = bc[t]; bls[t] = bl[t]; }

    // stage U = [x | y1 | y2] transposed to k-major
    for (int i = t; i < TR * 48; i += 256) {
        const int row = i / 48;
        const int q   = i % 48;
        const int seg = q >> 4;
        const int k4  = (q & 15) * 4;
        float4 v = make_float4(0.f, 0.f, 0.f, 0.f);
        if (row < nrows) {
            const size_t off = (size_t)(rowbase + row) * CC + k4;
            const float* p = (seg == 0) ? x : (seg == 1) ? g_y1 : g_y2;
            v = *(const float4*)(p + off);
        }
        const int kk = seg * CC + k4;
        Us[(kk + 0) * PITCH + row] = v.x;
        Us[(kk + 1) * PITCH + row] = v.y;
        Us[(kk + 2) * PITCH + row] = v.z;
        Us[(kk + 3) * PITCH + row] = v.w;
    }
    __syncthreads();

    const int tx = t & 15, ty = t >> 4;
    const int c0 = tx * 4, r0 = ty * 8;

    // phase 1: h = U @ Wc_flat
    unsigned long long acc[4][4];
#pragma unroll
    for (int p = 0; p < 4; p++)
#pragma unroll
        for (int c = 0; c < 4; c++) acc[p][c] = 0ULL;

#pragma unroll 2
    for (int k = 0; k < KC; k++) {
        const ulonglong2 A0 = *(const ulonglong2*)(Us + k * PITCH + r0);
        const ulonglong2 A1 = *(const ulonglong2*)(Us + k * PITCH + r0 + 4);
        unsigned long long ap[4] = {A0.x, A0.y, A1.x, A1.y};
        const float4 bv = *(const float4*)(Wcs + k * CC + c0);
        unsigned long long bb[4] = {pk2(bv.x), pk2(bv.y), pk2(bv.z), pk2(bv.w)};
#pragma unroll
        for (int p = 0; p < 4; p++)
#pragma unroll
            for (int c = 0; c < 4; c++)
                acc[p][c] = fma2(ap[p], bb[c], acc[p][c]);
    }

    __syncthreads();   // done reading Us — safe to overwrite with Hs

    // epilogue 1: bias + relu, store k-major into Hs (= Us region)
#pragma unroll
    for (int p = 0; p < 4; p++) {
#pragma unroll
        for (int c = 0; c < 4; c++) {
            float lo, hi;
            unpk2(acc[p][c], lo, hi);
            const float b = bcs[c0 + c];
            lo = fmaxf(lo + b, 0.f);
            hi = fmaxf(hi + b, 0.f);
            Us[(c0 + c) * PITCH + r0 + 2 * p]     = lo;
            Us[(c0 + c) * PITCH + r0 + 2 * p + 1] = hi;
        }
    }
    __syncthreads();

    // phase 2: out = h @ Wl
#pragma unroll
    for (int p = 0; p < 4; p++)
#pragma unroll
        for (int c = 0; c < 4; c++) acc[p][c] = 0ULL;

#pragma unroll 2
    for (int k = 0; k < CC; k++) {
        const ulonglong2 A0 = *(const ulonglong2*)(Us + k * PITCH + r0);
        const ulonglong2 A1 = *(const ulonglong2*)(Us + k * PITCH + r0 + 4);
        unsigned long long ap[4] = {A0.x, A0.y, A1.x, A1.y};
        const float4 bv = *(const float4*)(Wls + k * CC + c0);
        unsigned long long bb[4] = {pk2(bv.x), pk2(bv.y), pk2(bv.z), pk2(bv.w)};
#pragma unroll
        for (int p = 0; p < 4; p++)
#pragma unroll
            for (int c = 0; c < 4; c++)
                acc[p][c] = fma2(ap[p], bb[c], acc[p][c]);
    }

    // epilogue 2: bias + store
#pragma unroll
    for (int p = 0; p < 4; p++) {
        float lo[4], hi[4];
#pragma unroll
        for (int c = 0; c < 4; c++) {
            unpk2(acc[p][c], lo[c], hi[c]);
            const float b = bls[c0 + c];
            lo[c] += b; hi[c] += b;
        }
        const int rlo = r0 + 2 * p;
        if (rlo < nrows) {
            float4 v = make_float4(lo[0], lo[1], lo[2], lo[3]);
            *(float4*)(out + (size_t)(rowbase + rlo) * CC + c0) = v;
        }
        if (rlo + 1 < nrows) {
            float4 v = make_float4(hi[0], hi[1], hi[2], hi[3]);
            *(float4*)(out + (size_t)(rowbase + rlo + 1) * CC + c0) = v;
        }
    }
}

// ---------------- launch ----------------
extern "C" void kernel_launch(void* const* d_in, const int* in_sizes, int n_in,
                              void* d_out, int out_size) {
    const float* x   = (const float*)d_in[0];
    const int*   src = (const int*)d_in[1];
    const int*   dst = (const int*)d_in[2];
    const float* Wc  = (const float*)d_in[3];
    const float* bc  = (const float*)d_in[4];
    const float* Wl  = (const float*)d_in[5];
    const float* bl  = (const float*)d_in[6];
    float* out = (float*)d_out;

    static bool attr_set = false;
    const int fused_smem = (KC * PITCH + KC * CC + CC * CC + 2 * CC) * 4;
    if (!attr_set) {
        cudaFuncSetAttribute(k_fused, cudaFuncAttributeMaxDynamicSharedMemorySize,
                             fused_smem);
        attr_set = true;
    }

    float* y1;
    float* y2;
    cudaGetSymbolAddress((void**)&y1, g_y1);
    cudaGetSymbolAddress((void**)&y2, g_y2);

    k_zero_deg<<<(NN + 255) / 256, 256>>>();
    k_degree<<<(EE + 255) / 256, 256>>>(dst);
    k_norm<<<(NN + 255) / 256, 256>>>();
    k_scan<<<1, 1024>>>();
    k_fill<<<(EE + 255) / 256, 256>>>(src, dst);

    // y1 = -(A x)
    k_spmm<<<(NN + 7) / 8, 256>>>(x, x, y1, -1.f, 0.f);
    // y2 = -2 (A y1) - x
    k_spmm<<<(NN + 7) / 8, 256>>>(y1, x, y2, -2.f, -1.f);

    const int nblk = (NROWS + TR - 1) / TR;
    k_fused<<<nblk, 256, fused_smem>>>(x, Wc, bc, Wl, bl, out);
}

// round 3
// speedup vs baseline: 1.1545x; 1.1545x over previous
#include <cuda_runtime.h>
#include <cstdint>

// Problem constants (from reference)
#define NN 50000
#define EE 800000
#define BB 4
#define CC 64
#define NROWS (BB*NN)          // 200000 rows of 64 features
#define SBS 256
#define SNB ((NN + SBS - 1) / SBS)   // 196 scan blocks

// ---------------- scratch (device globals) ----------------
__device__ int   g_deg[NN];
__device__ float g_norm[NN];
__device__ int   g_rowptr[NN + 1];
__device__ int   g_fill[NN];
__device__ int2  g_edge[EE];          // (src, weight-bits) interleaved
__device__ int   g_bsum[SNB];
__device__ int   g_boff[SNB];
__device__ float g_y1[(size_t)NROWS * CC];
__device__ float g_y2[(size_t)NROWS * CC];

// ---------------- packed f32x2 helpers ----------------
__device__ __forceinline__ unsigned long long pk2(float f) {
    unsigned long long r; unsigned u = __float_as_uint(f);
    asm("mov.b64 %0, {%1, %1};" : "=l"(r) : "r"(u));
    return r;
}
__device__ __forceinline__ unsigned long long fma2(unsigned long long a,
                                                   unsigned long long b,
                                                   unsigned long long c) {
    unsigned long long d;
    asm("fma.rn.f32x2 %0, %1, %2, %3;" : "=l"(d) : "l"(a), "l"(b), "l"(c));
    return d;
}
__device__ __forceinline__ void unpk2(unsigned long long v, float& lo, float& hi) {
    unsigned a, b;
    asm("mov.b64 {%0, %1}, %2;" : "=r"(a), "=r"(b) : "l"(v));
    lo = __uint_as_float(a); hi = __uint_as_float(b);
}

// ---------------- graph prep ----------------
__global__ void k_zero_deg() {
    int i = blockIdx.x * blockDim.x + threadIdx.x;
    if (i < NN) g_deg[i] = 0;
}

__global__ void k_degree(const int* __restrict__ dst) {
    int e = blockIdx.x * blockDim.x + threadIdx.x;
    if (e < EE) atomicAdd(&g_deg[dst[e]], 1);
}

// per-block partial sums of g_deg
__global__ void k_part() {
    __shared__ int sh[SBS];
    const int t = threadIdx.x;
    const int i = blockIdx.x * SBS + t;
    int v = (i < NN) ? g_deg[i] : 0;
    sh[t] = v;
    __syncthreads();
    for (int off = SBS / 2; off > 0; off >>= 1) {
        if (t < off) sh[t] += sh[t + off];
        __syncthreads();
    }
    if (t == 0) g_bsum[blockIdx.x] = sh[0];
}

// 1-block scan of the SNB partial sums -> exclusive block offsets
__global__ void k_scan2() {
    __shared__ int sh[SBS];
    const int t = threadIdx.x;
    int v = (t < SNB) ? g_bsum[t] : 0;
    sh[t] = v;
    __syncthreads();
    for (int off = 1; off < SBS; off <<= 1) {
        int u = (t >= off) ? sh[t - off] : 0;
        __syncthreads();
        sh[t] += u;
        __syncthreads();
    }
    if (t < SNB) g_boff[t] = sh[t] - v;     // exclusive
    if (t == SNB - 1) g_rowptr[NN] = sh[t]; // total (== EE)
}

// per-block exclusive scan + emit rowptr/fill, fused norm
__global__ void k_emit() {
    __shared__ int sh[SBS];
    const int t = threadIdx.x;
    const int i = blockIdx.x * SBS + t;
    int d = (i < NN) ? g_deg[i] : 0;
    sh[t] = d;
    __syncthreads();
    for (int off = 1; off < SBS; off <<= 1) {
        int u = (t >= off) ? sh[t - off] : 0;
        __syncthreads();
        sh[t] += u;
        __syncthreads();
    }
    if (i < NN) {
        int rp = g_boff[blockIdx.x] + sh[t] - d;   // exclusive prefix
        g_rowptr[i] = rp;
        g_fill[i]   = rp;
        g_norm[i]   = rsqrtf((float)(d < 1 ? 1 : d));
    }
}

__global__ void k_fill(const int* __restrict__ src, const int* __restrict__ dst) {
    int e = blockIdx.x * blockDim.x + threadIdx.x;
    if (e < EE) {
        int d = dst[e];
        int s = src[e];
        int p = atomicAdd(&g_fill[d], 1);
        g_edge[p] = make_int2(s, __float_as_int(g_norm[s] * g_norm[d]));
    }
}

// ---------------- SPMM: out = alpha*(A_hat @ in) + beta*add ----------------
__global__ void k_spmm(const float* __restrict__ in, const float* __restrict__ addv,
                       float* __restrict__ out, float alpha, float beta) {
    const int warp = (blockIdx.x * blockDim.x + threadIdx.x) >> 5;
    if (warp >= NN) return;
    const int node = warp;
    const int lane = threadIdx.x & 31;
    const int bhalf = lane >> 4;             // 0 or 1
    const int c4 = (lane & 15) * 4;          // channel quad base

    float4 acc0 = make_float4(0.f, 0.f, 0.f, 0.f);
    float4 acc1 = make_float4(0.f, 0.f, 0.f, 0.f);

    const int s0 = g_rowptr[node];
    const int s1 = g_rowptr[node + 1];
    const size_t rowA = (size_t)(bhalf       * NN) * CC + c4;
    const size_t rowB = (size_t)((bhalf + 2) * NN) * CC + c4;

    for (int e = s0; e < s1; e++) {
        const int2 ev = g_edge[e];
        const int   s = ev.x;
        const float w = __int_as_float(ev.y);
        const size_t boff = (size_t)s * CC;
        float4 v0 = *(const float4*)(in + rowA + boff);
        float4 v1 = *(const float4*)(in + rowB + boff);
        acc0.x += w * v0.x; acc0.y += w * v0.y; acc0.z += w * v0.z; acc0.w += w * v0.w;
        acc1.x += w * v1.x; acc1.y += w * v1.y; acc1.z += w * v1.z; acc1.w += w * v1.w;
    }

    const size_t noff = (size_t)node * CC;
    float4 o0, o1;
    o0.x = alpha * acc0.x; o0.y = alpha * acc0.y; o0.z = alpha * acc0.z; o0.w = alpha * acc0.w;
    o1.x = alpha * acc1.x; o1.y = alpha * acc1.y; o1.z = alpha * acc1.z; o1.w = alpha * acc1.w;
    if (beta != 0.f) {
        float4 a0 = *(const float4*)(addv + rowA + noff);
        float4 a1 = *(const float4*)(addv + rowB + noff);
        o0.x += beta * a0.x; o0.y += beta * a0.y; o0.z += beta * a0.z; o0.w += beta * a0.w;
        o1.x += beta * a1.x; o1.y += beta * a1.y; o1.z += beta * a1.z; o1.w += beta * a1.w;
    }
    *(float4*)(out + rowA + noff) = o0;
    *(float4*)(out + rowB + noff) = o1;
}

// ---------------- fused dense: out = relu([x|y1|y2] Wc + bc) Wl + bl ----------
// tile: 128 rows x 64 cols, 256 threads.
// warp w -> 8 cols (B loads are warp-uniform => smem broadcast);
// lane l -> 4 rows (2 packed f32x2 pairs). Thread tile = 4r x 8c = 16 fma2/k.
#define TR 128
#define KC 192
#define PITCH 132     // floats per k-row of Us

__global__ void __launch_bounds__(256, 1)
k_fused(const float* __restrict__ x,
        const float* __restrict__ Wc, const float* __restrict__ bc,
        const float* __restrict__ Wl, const float* __restrict__ bl,
        float* __restrict__ out) {
    extern __shared__ float sm[];
    float* Us  = sm;                    // [KC][PITCH], reused as Hs [64][PITCH]
    float* Wcs = sm + KC * PITCH;       // [192][64]
    float* Wls = Wcs + KC * CC;         // [64][64]
    float* bcs = Wls + CC * CC;         // [64]
    float* bls = bcs + CC;              // [64]

    const int t = threadIdx.x;
    const int rowbase = blockIdx.x * TR;
    const int nrows = min(TR, NROWS - rowbase);

    // stage weights
    for (int i = t; i < (KC * CC) / 4; i += 256)
        ((float4*)Wcs)[i] = ((const float4*)Wc)[i];
    for (int i = t; i < (CC * CC) / 4; i += 256)
        ((float4*)Wls)[i] = ((const float4*)Wl)[i];
    if (t < CC) { bcs[t] = bc[t]; bls[t] = bl[t]; }

    // stage U = [x | y1 | y2] transposed to k-major
    for (int i = t; i < TR * 48; i += 256) {
        const int row = i / 48;
        const int q   = i % 48;
        const int seg = q >> 4;
        const int k4  = (q & 15) * 4;
        float4 v = make_float4(0.f, 0.f, 0.f, 0.f);
        if (row < nrows) {
            const size_t off = (size_t)(rowbase + row) * CC + k4;
            const float* p = (seg == 0) ? x : (seg == 1) ? g_y1 : g_y2;
            v = *(const float4*)(p + off);
        }
        const int kk = seg * CC + k4;
        Us[(kk + 0) * PITCH + row] = v.x;
        Us[(kk + 1) * PITCH + row] = v.y;
        Us[(kk + 2) * PITCH + row] = v.z;
        Us[(kk + 3) * PITCH + row] = v.w;
    }
    __syncthreads();

    const int w  = t >> 5;         // warp -> column block
    const int l  = t & 31;         // lane -> row group
    const int c0 = w * 8;
    const int r0 = l * 4;

    // phase 1: h = U @ Wc_flat
    unsigned long long acc[2][8];
#pragma unroll
    for (int p = 0; p < 2; p++)
#pragma unroll
        for (int c = 0; c < 8; c++) acc[p][c] = 0ULL;

#pragma unroll 2
    for (int k = 0; k < KC; k++) {
        const ulonglong2 A = *(const ulonglong2*)(Us + k * PITCH + r0);
        unsigned long long ap[2] = {A.x, A.y};
        const float4 b0 = *(const float4*)(Wcs + k * CC + c0);      // warp-uniform
        const float4 b1 = *(const float4*)(Wcs + k * CC + c0 + 4);  // warp-uniform
        unsigned long long bb[8] = {pk2(b0.x), pk2(b0.y), pk2(b0.z), pk2(b0.w),
                                    pk2(b1.x), pk2(b1.y), pk2(b1.z), pk2(b1.w)};
#pragma unroll
        for (int p = 0; p < 2; p++)
#pragma unroll
            for (int c = 0; c < 8; c++)
                acc[p][c] = fma2(ap[p], bb[c], acc[p][c]);
    }

    __syncthreads();   // done reading Us — safe to overwrite with Hs

    // epilogue 1: bias + relu, store k-major into Hs (= Us region)
#pragma unroll
    for (int p = 0; p < 2; p++) {
#pragma unroll
        for (int c = 0; c < 8; c++) {
            float lo, hi;
            unpk2(acc[p][c], lo, hi);
            const float b = bcs[c0 + c];
            lo = fmaxf(lo + b, 0.f);
            hi = fmaxf(hi + b, 0.f);
            Us[(c0 + c) * PITCH + r0 + 2 * p]     = lo;
            Us[(c0 + c) * PITCH + r0 + 2 * p + 1] = hi;
        }
    }
    __syncthreads();

    // phase 2: out = h @ Wl
#pragma unroll
    for (int p = 0; p < 2; p++)
#pragma unroll
        for (int c = 0; c < 8; c++) acc[p][c] = 0ULL;

#pragma unroll 2
    for (int k = 0; k < CC; k++) {
        const ulonglong2 A = *(const ulonglong2*)(Us + k * PITCH + r0);
        unsigned long long ap[2] = {A.x, A.y};
        const float4 b0 = *(const float4*)(Wls + k * CC + c0);
        const float4 b1 = *(const float4*)(Wls + k * CC + c0 + 4);
        unsigned long long bb[8] = {pk2(b0.x), pk2(b0.y), pk2(b0.z), pk2(b0.w),
                                    pk2(b1.x), pk2(b1.y), pk2(b1.z), pk2(b1.w)};
#pragma unroll
        for (int p = 0; p < 2; p++)
#pragma unroll
            for (int c = 0; c < 8; c++)
                acc[p][c] = fma2(ap[p], bb[c], acc[p][c]);
    }

    // epilogue 2: bias + store (thread owns rows r0..r0+3, cols c0..c0+7)
    float res[4][8];
#pragma unroll
    for (int p = 0; p < 2; p++)
#pragma unroll
        for (int c = 0; c < 8; c++) {
            float lo, hi;
            unpk2(acc[p][c], lo, hi);
            const float b = bls[c0 + c];
            res[2 * p][c]     = lo + b;
            res[2 * p + 1][c] = hi + b;
        }
#pragma unroll
    for (int j = 0; j < 4; j++) {
        const int r = r0 + j;
        if (r < nrows) {
            float* op = out + (size_t)(rowbase + r) * CC + c0;
            *(float4*)(op)     = make_float4(res[j][0], res[j][1], res[j][2], res[j][3]);
            *(float4*)(op + 4) = make_float4(res[j][4], res[j][5], res[j][6], res[j][7]);
        }
    }
}

// ---------------- launch ----------------
extern "C" void kernel_launch(void* const* d_in, const int* in_sizes, int n_in,
                              void* d_out, int out_size) {
    const float* x   = (const float*)d_in[0];
    const int*   src = (const int*)d_in[1];
    const int*   dst = (const int*)d_in[2];
    const float* Wc  = (const float*)d_in[3];
    const float* bc  = (const float*)d_in[4];
    const float* Wl  = (const float*)d_in[5];
    const float* bl  = (const float*)d_in[6];
    float* out = (float*)d_out;

    static bool attr_set = false;
    const int fused_smem = (KC * PITCH + KC * CC + CC * CC + 2 * CC) * 4;
    if (!attr_set) {
        cudaFuncSetAttribute(k_fused, cudaFuncAttributeMaxDynamicSharedMemorySize,
                             fused_smem);
        attr_set = true;
    }

    float* y1;
    float* y2;
    cudaGetSymbolAddress((void**)&y1, g_y1);
    cudaGetSymbolAddress((void**)&y2, g_y2);

    k_zero_deg<<<(NN + 255) / 256, 256>>>();
    k_degree<<<(EE + 255) / 256, 256>>>(dst);
    k_part<<<SNB, SBS>>>();
    k_scan2<<<1, SBS>>>();
    k_emit<<<SNB, SBS>>>();
    k_fill<<<(EE + 255) / 256, 256>>>(src, dst);

    // y1 = -(A x)
    k_spmm<<<(NN + 7) / 8, 256>>>(x, x, y1, -1.f, 0.f);
    // y2 = -2 (A y1) - x
    k_spmm<<<(NN + 7) / 8, 256>>>(y1, x, y2, -2.f, -1.f);

    const int nblk = (NROWS + TR - 1) / TR;
    k_fused<<<nblk, 256, fused_smem>>>(x, Wc, bc, Wl, bl, out);
}

// round 4
// speedup vs baseline: 1.2009x; 1.0402x over previous
#include <cuda_runtime.h>
#include <cuda_fp16.h>
#include <cstdint>

// Problem constants (from reference)
#define NN 50000
#define EE 800000
#define BB 4
#define CC 64
#define NROWS (BB*NN)          // 200000 rows of 64 features
#define SBS 256
#define SNB ((NN + SBS - 1) / SBS)   // 196 scan blocks

// ---------------- scratch (device globals) ----------------
__device__ int    g_deg[NN];
__device__ float  g_norm[NN];
__device__ int    g_rowptr[NN + 1];
__device__ int    g_fill[NN];
__device__ int2   g_edge[EE];          // (src, weight-bits)
__device__ int    g_bsum[SNB];
__device__ float  g_y1[(size_t)NROWS * CC];
__device__ float  g_y2[(size_t)NROWS * CC];
__device__ __half g_xh[(size_t)NROWS * CC];
__device__ __half g_y1h[(size_t)NROWS * CC];

// ---------------- packed f32x2 helpers ----------------
__device__ __forceinline__ unsigned long long pk2(float f) {
    unsigned long long r; unsigned u = __float_as_uint(f);
    asm("mov.b64 %0, {%1, %1};" : "=l"(r) : "r"(u));
    return r;
}
__device__ __forceinline__ unsigned long long fma2(unsigned long long a,
                                                   unsigned long long b,
                                                   unsigned long long c) {
    unsigned long long d;
    asm("fma.rn.f32x2 %0, %1, %2, %3;" : "=l"(d) : "l"(a), "l"(b), "l"(c));
    return d;
}
__device__ __forceinline__ void unpk2(unsigned long long v, float& lo, float& hi) {
    unsigned a, b;
    asm("mov.b64 {%0, %1}, %2;" : "=r"(a), "=r"(b) : "l"(v));
    lo = __uint_as_float(a); hi = __uint_as_float(b);
}

// ---------------- graph prep ----------------
__global__ void k_degree(const int* __restrict__ dst) {
    int e = blockIdx.x * blockDim.x + threadIdx.x;
    if (e < EE) atomicAdd(&g_deg[dst[e]], 1);
}

// per-block partial sums of g_deg
__global__ void k_part() {
    __shared__ int sh[SBS];
    const int t = threadIdx.x;
    const int i = blockIdx.x * SBS + t;
    sh[t] = (i < NN) ? g_deg[i] : 0;
    __syncthreads();
    for (int off = SBS / 2; off > 0; off >>= 1) {
        if (t < off) sh[t] += sh[t + off];
        __syncthreads();
    }
    if (t == 0) g_bsum[blockIdx.x] = sh[0];
}

// per-block: offset = sum of previous block partials, then local scan + emit
__global__ void k_emit() {
    __shared__ int sh[SBS];
    const int t = threadIdx.x;
    const int i = blockIdx.x * SBS + t;

    // 1) block offset = sum_{j < blockIdx.x} g_bsum[j]
    sh[t] = (t < blockIdx.x && t < SNB) ? g_bsum[t] : 0;
    __syncthreads();
    for (int off = SBS / 2; off > 0; off >>= 1) {
        if (t < off) sh[t] += sh[t + off];
        __syncthreads();
    }
    const int boff = sh[0];
    __syncthreads();

    // 2) local inclusive scan of degrees
    const int d = (i < NN) ? g_deg[i] : 0;
    sh[t] = d;
    __syncthreads();
    for (int off = 1; off < SBS; off <<= 1) {
        int u = (t >= off) ? sh[t - off] : 0;
        __syncthreads();
        sh[t] += u;
        __syncthreads();
    }
    if (i < NN) {
        const int rp = boff + sh[t] - d;   // exclusive prefix
        g_rowptr[i] = rp;
        g_fill[i]   = rp;
        g_norm[i]   = rsqrtf((float)(d < 1 ? 1 : d));
    }
    if (i == 0) g_rowptr[NN] = EE;
}

__global__ void k_fill(const int* __restrict__ src, const int* __restrict__ dst) {
    int e = blockIdx.x * blockDim.x + threadIdx.x;
    if (e < EE) {
        int d = dst[e];
        int s = src[e];
        int p = atomicAdd(&g_fill[d], 1);
        g_edge[p] = make_int2(s, __float_as_int(g_norm[s] * g_norm[d]));
    }
}

// ---------------- fp32 -> fp16 conversion (8 elems / thread) ----------------
__global__ void k_x2h(const float* __restrict__ x) {
    const size_t i = (size_t)(blockIdx.x * blockDim.x + threadIdx.x) * 8;
    if (i >= (size_t)NROWS * CC) return;
    float4 a = *(const float4*)(x + i);
    float4 b = *(const float4*)(x + i + 4);
    __half2 h[4];
    h[0] = __floats2half2_rn(a.x, a.y);
    h[1] = __floats2half2_rn(a.z, a.w);
    h[2] = __floats2half2_rn(b.x, b.y);
    h[3] = __floats2half2_rn(b.z, b.w);
    *(uint4*)(g_xh + i) = *(uint4*)h;
}

// ---------------- SPMM (fp16 gather, fp32 accumulate) ----------------
// out_f = alpha*(A_hat @ in_h) + beta*addv ; optionally also emit fp16 copy.
// 1 warp per dst node; lane -> (batch = lane>>3, chan-octet = (lane&7)*8).
// Per edge per lane: one 16B load (8 halves).
__global__ void k_spmm_h(const __half* __restrict__ in_h,
                         const float* __restrict__ addv,
                         float* __restrict__ out_f,
                         __half* __restrict__ out_h,
                         float alpha, float beta) {
    const int warp = (blockIdx.x * blockDim.x + threadIdx.x) >> 5;
    if (warp >= NN) return;
    const int node = warp;
    const int lane = threadIdx.x & 31;
    const int b  = lane >> 3;            // batch 0..3
    const int c8 = (lane & 7) * 8;       // channel octet base

    const __half* base = in_h + (size_t)b * NN * CC + c8;

    float acc[8];
#pragma unroll
    for (int j = 0; j < 8; j++) acc[j] = 0.f;

    const int s0 = g_rowptr[node];
    const int s1 = g_rowptr[node + 1];

#pragma unroll 4
    for (int e = s0; e < s1; e++) {
        const int2 ev = g_edge[e];
        const float w = __int_as_float(ev.y);
        uint4 v = *(const uint4*)(base + (size_t)ev.x * CC);
        const __half2* hp = (const __half2*)&v;
#pragma unroll
        for (int j = 0; j < 4; j++) {
            float2 f = __half22float2(hp[j]);
            acc[2 * j]     += w * f.x;
            acc[2 * j + 1] += w * f.y;
        }
    }

    const size_t o = ((size_t)b * NN + node) * CC + c8;
    float r[8];
#pragma unroll
    for (int j = 0; j < 8; j++) r[j] = alpha * acc[j];
    if (beta != 0.f) {
        float4 a0 = *(const float4*)(addv + o);
        float4 a1 = *(const float4*)(addv + o + 4);
        r[0] += beta * a0.x; r[1] += beta * a0.y; r[2] += beta * a0.z; r[3] += beta * a0.w;
        r[4] += beta * a1.x; r[5] += beta * a1.y; r[6] += beta * a1.z; r[7] += beta * a1.w;
    }
    *(float4*)(out_f + o)     = make_float4(r[0], r[1], r[2], r[3]);
    *(float4*)(out_f + o + 4) = make_float4(r[4], r[5], r[6], r[7]);
    if (out_h != nullptr) {
        __half2 h[4];
        h[0] = __floats2half2_rn(r[0], r[1]);
        h[1] = __floats2half2_rn(r[2], r[3]);
        h[2] = __floats2half2_rn(r[4], r[5]);
        h[3] = __floats2half2_rn(r[6], r[7]);
        *(uint4*)(out_h + o) = *(uint4*)h;
    }
}

// ---------------- fused dense: out = relu([x|y1|y2] Wc + bc) Wl + bl ----------
// tile: 128 rows x 64 cols, 256 threads.
// warp -> 8 cols (B loads warp-uniform => smem broadcast); lane -> 4 rows.
#define TR 128
#define KC 192
#define PITCH 132     // floats per k-row of Us

__global__ void __launch_bounds__(256, 1)
k_fused(const float* __restrict__ x,
        const float* __restrict__ Wc, const float* __restrict__ bc,
        const float* __restrict__ Wl, const float* __restrict__ bl,
        float* __restrict__ out) {
    extern __shared__ float sm[];
    float* Us  = sm;                    // [KC][PITCH], reused as Hs [64][PITCH]
    float* Wcs = sm + KC * PITCH;       // [192][64]
    float* Wls = Wcs + KC * CC;         // [64][64]
    float* bcs = Wls + CC * CC;         // [64]
    float* bls = bcs + CC;              // [64]

    const int t = threadIdx.x;
    const int rowbase = blockIdx.x * TR;
    const int nrows = min(TR, NROWS - rowbase);

    // stage weights
    for (int i = t; i < (KC * CC) / 4; i += 256)
        ((float4*)Wcs)[i] = ((const float4*)Wc)[i];
    for (int i = t; i < (CC * CC) / 4; i += 256)
        ((float4*)Wls)[i] = ((const float4*)Wl)[i];
    if (t < CC) { bcs[t] = bc[t]; bls[t] = bl[t]; }

    // stage U = [x | y1 | y2] transposed to k-major
    for (int i = t; i < TR * 48; i += 256) {
        const int row = i / 48;
        const int q   = i % 48;
        const int seg = q >> 4;
        const int k4  = (q & 15) * 4;
        float4 v = make_float4(0.f, 0.f, 0.f, 0.f);
        if (row < nrows) {
            const size_t off = (size_t)(rowbase + row) * CC + k4;
            const float* p = (seg == 0) ? x : (seg == 1) ? g_y1 : g_y2;
            v = *(const float4*)(p + off);
        }
        const int kk = seg * CC + k4;
        Us[(kk + 0) * PITCH + row] = v.x;
        Us[(kk + 1) * PITCH + row] = v.y;
        Us[(kk + 2) * PITCH + row] = v.z;
        Us[(kk + 3) * PITCH + row] = v.w;
    }
    __syncthreads();

    const int w  = t >> 5;
    const int l  = t & 31;
    const int c0 = w * 8;
    const int r0 = l * 4;

    // phase 1: h = U @ Wc_flat
    unsigned long long acc[2][8];
#pragma unroll
    for (int p = 0; p < 2; p++)
#pragma unroll
        for (int c = 0; c < 8; c++) acc[p][c] = 0ULL;

#pragma unroll 2
    for (int k = 0; k < KC; k++) {
        const ulonglong2 A = *(const ulonglong2*)(Us + k * PITCH + r0);
        unsigned long long ap[2] = {A.x, A.y};
        const float4 b0 = *(const float4*)(Wcs + k * CC + c0);
        const float4 b1 = *(const float4*)(Wcs + k * CC + c0 + 4);
        unsigned long long bb[8] = {pk2(b0.x), pk2(b0.y), pk2(b0.z), pk2(b0.w),
                                    pk2(b1.x), pk2(b1.y), pk2(b1.z), pk2(b1.w)};
#pragma unroll
        for (int p = 0; p < 2; p++)
#pragma unroll
            for (int c = 0; c < 8; c++)
                acc[p][c] = fma2(ap[p], bb[c], acc[p][c]);
    }

    __syncthreads();

    // epilogue 1: bias + relu -> Hs (k-major, reuses Us)
#pragma unroll
    for (int p = 0; p < 2; p++) {
#pragma unroll
        for (int c = 0; c < 8; c++) {
            float lo, hi;
            unpk2(acc[p][c], lo, hi);
            const float b = bcs[c0 + c];
            lo = fmaxf(lo + b, 0.f);
            hi = fmaxf(hi + b, 0.f);
            Us[(c0 + c) * PITCH + r0 + 2 * p]     = lo;
            Us[(c0 + c) * PITCH + r0 + 2 * p + 1] = hi;
        }
    }
    __syncthreads();

    // phase 2: out = h @ Wl
#pragma unroll
    for (int p = 0; p < 2; p++)
#pragma unroll
        for (int c = 0; c < 8; c++) acc[p][c] = 0ULL;

#pragma unroll 2
    for (int k = 0; k < CC; k++) {
        const ulonglong2 A = *(const ulonglong2*)(Us + k * PITCH + r0);
        unsigned long long ap[2] = {A.x, A.y};
        const float4 b0 = *(const float4*)(Wls + k * CC + c0);
        const float4 b1 = *(const float4*)(Wls + k * CC + c0 + 4);
        unsigned long long bb[8] = {pk2(b0.x), pk2(b0.y), pk2(b0.z), pk2(b0.w),
                                    pk2(b1.x), pk2(b1.y), pk2(b1.z), pk2(b1.w)};
#pragma unroll
        for (int p = 0; p < 2; p++)
#pragma unroll
            for (int c = 0; c < 8; c++)
                acc[p][c] = fma2(ap[p], bb[c], acc[p][c]);
    }

    // epilogue 2: bias + store
    float res[4][8];
#pragma unroll
    for (int p = 0; p < 2; p++)
#pragma unroll
        for (int c = 0; c < 8; c++) {
            float lo, hi;
            unpk2(acc[p][c], lo, hi);
            const float b = bls[c0 + c];
            res[2 * p][c]     = lo + b;
            res[2 * p + 1][c] = hi + b;
        }
#pragma unroll
    for (int j = 0; j < 4; j++) {
        const int r = r0 + j;
        if (r < nrows) {
            float* op = out + (size_t)(rowbase + r) * CC + c0;
            *(float4*)(op)     = make_float4(res[j][0], res[j][1], res[j][2], res[j][3]);
            *(float4*)(op + 4) = make_float4(res[j][4], res[j][5], res[j][6], res[j][7]);
        }
    }
}

// ---------------- launch ----------------
extern "C" void kernel_launch(void* const* d_in, const int* in_sizes, int n_in,
                              void* d_out, int out_size) {
    const float* x   = (const float*)d_in[0];
    const int*   src = (const int*)d_in[1];
    const int*   dst = (const int*)d_in[2];
    const float* Wc  = (const float*)d_in[3];
    const float* bc  = (const float*)d_in[4];
    const float* Wl  = (const float*)d_in[5];
    const float* bl  = (const float*)d_in[6];
    float* out = (float*)d_out;

    static bool attr_set = false;
    const int fused_smem = (KC * PITCH + KC * CC + CC * CC + 2 * CC) * 4;
    if (!attr_set) {
        cudaFuncSetAttribute(k_fused, cudaFuncAttributeMaxDynamicSharedMemorySize,
                             fused_smem);
        attr_set = true;
    }

    float *y1, *y2; __half *xh, *y1h; int* degp;
    cudaGetSymbolAddress((void**)&y1,  g_y1);
    cudaGetSymbolAddress((void**)&y2,  g_y2);
    cudaGetSymbolAddress((void**)&xh,  g_xh);
    cudaGetSymbolAddress((void**)&y1h, g_y1h);
    cudaGetSymbolAddress((void**)&degp, g_deg);

    cudaMemsetAsync(degp, 0, NN * sizeof(int));
    k_degree<<<(EE + 255) / 256, 256>>>(dst);
    k_part<<<SNB, SBS>>>();
    k_emit<<<SNB, SBS>>>();
    k_fill<<<(EE + 255) / 256, 256>>>(src, dst);

    // x -> fp16 (independent of graph prep; scheduled early for overlap)
    k_x2h<<<(NROWS * CC / 8 + 255) / 256, 256>>>(x);

    // y1 = -(A xh)        (emit fp32 + fp16)
    k_spmm_h<<<(NN + 7) / 8, 256>>>(xh, nullptr, y1, y1h, -1.f, 0.f);
    // y2 = -2 (A y1h) - x (fp32 only)
    k_spmm_h<<<(NN + 7) / 8, 256>>>(y1h, x, y2, nullptr, -2.f, -1.f);

    const int nblk = (NROWS + TR - 1) / TR;
    k_fused<<<nblk, 256, fused_smem>>>(x, Wc, bc, Wl, bl, out);
}

// round 5
// speedup vs baseline: 1.2951x; 1.0784x over previous
#include <cuda_runtime.h>
#include <cuda_fp16.h>
#include <cstdint>

// Problem constants
#define NN 50000
#define EE 800000
#define BB 4
#define CC 64
#define NROWS (BB*NN)
#define SBS 256
#define SNB ((NN + SBS - 1) / SBS)

// ---------------- scratch (device globals) ----------------
__device__ int    g_deg[NN];          // zero at load; re-zeroed by k_fill3 each run
__device__ float  g_norm[NN];
__device__ int    g_rowptr[NN + 1];
__device__ int    g_fill[NN];
__device__ int2   g_edge[EE];         // (src, weight-bits)
__device__ __half g_xh[(size_t)NROWS * CC];
__device__ __half g_y1h[(size_t)NROWS * CC];
__device__ __half g_y2h[(size_t)NROWS * CC];

// ---------------- packed f32x2 helpers ----------------
__device__ __forceinline__ unsigned long long fma2(unsigned long long a,
                                                   unsigned long long b,
                                                   unsigned long long c) {
    unsigned long long d;
    asm("fma.rn.f32x2 %0, %1, %2, %3;" : "=l"(d) : "l"(a), "l"(b), "l"(c));
    return d;
}
__device__ __forceinline__ void unpk2(unsigned long long v, float& lo, float& hi) {
    unsigned a, b;
    asm("mov.b64 {%0, %1}, %2;" : "=r"(a), "=r"(b) : "l"(v));
    lo = __uint_as_float(a); hi = __uint_as_float(b);
}

// ---------------- launch 1: degree ----------------
__global__ void k_degree(const int* __restrict__ dst) {
    int e = blockIdx.x * blockDim.x + threadIdx.x;
    if (e < EE) atomicAdd(&g_deg[dst[e]], 1);
}

// ---------------- launch 2: scan + emit (self-sufficient) ----------------
__global__ void k_emit2() {
    __shared__ int sh[SBS];
    const int t = threadIdx.x;
    const int i = blockIdx.x * SBS + t;

    // block offset = sum g_deg[0 .. blockIdx.x*SBS)
    const int lim = blockIdx.x * SBS;      // multiple of 256 -> int4-aligned
    int s = 0;
    for (int j = t * 4; j < lim; j += SBS * 4) {
        int4 v = *(const int4*)(g_deg + j);
        s += v.x + v.y + v.z + v.w;
    }
    sh[t] = s;
    __syncthreads();
    for (int off = SBS / 2; off > 0; off >>= 1) {
        if (t < off) sh[t] += sh[t + off];
        __syncthreads();
    }
    const int boff = sh[0];
    __syncthreads();

    // local inclusive scan
    const int d = (i < NN) ? g_deg[i] : 0;
    sh[t] = d;
    __syncthreads();
    for (int off = 1; off < SBS; off <<= 1) {
        int u = (t >= off) ? sh[t - off] : 0;
        __syncthreads();
        sh[t] += u;
        __syncthreads();
    }
    if (i < NN) {
        const int rp = boff + sh[t] - d;
        g_rowptr[i] = rp;
        g_fill[i]   = rp;
        g_norm[i]   = rsqrtf((float)(d < 1 ? 1 : d));
    }
    if (i == 0) g_rowptr[NN] = EE;
}

// ---------------- launch 3: fill edges + x->fp16 + re-zero deg ----------------
// grid sized for x2h (NROWS*CC/8 = 1.6M threads)
__global__ void k_fill3(const int* __restrict__ src, const int* __restrict__ dst,
                        const float* __restrict__ x) {
    const int tid = blockIdx.x * blockDim.x + threadIdx.x;

    // x -> fp16 (8 elems/thread)
    const size_t i8 = (size_t)tid * 8;
    if (i8 < (size_t)NROWS * CC) {
        float4 a = *(const float4*)(x + i8);
        float4 b = *(const float4*)(x + i8 + 4);
        __half2 h[4];
        h[0] = __floats2half2_rn(a.x, a.y);
        h[1] = __floats2half2_rn(a.z, a.w);
        h[2] = __floats2half2_rn(b.x, b.y);
        h[3] = __floats2half2_rn(b.z, b.w);
        *(uint4*)(g_xh + i8) = *(uint4*)h;
    }

    // edge fill
    if (tid < EE) {
        const int d = dst[tid];
        const int s = src[tid];
        const int p = atomicAdd(&g_fill[d], 1);
        g_edge[p] = make_int2(s, __float_as_int(g_norm[s] * g_norm[d]));
    }

    // re-zero g_deg for the next replay (no kernel reads g_deg after k_emit2)
    if (tid < NN / 4) ((int4*)g_deg)[tid] = make_int4(0, 0, 0, 0);
}

// ---------------- launches 4,5: SPMM (fp16 gather, fp32 acc, fp16 out) -------
// out_h = fp16( alpha*(A_hat @ in_h) + beta*addx )
// 1 warp per dst node; lane -> (batch = lane>>3, chan-octet = (lane&7)*8)
__global__ void k_spmm_h(const __half* __restrict__ in_h,
                         const float* __restrict__ addx,
                         __half* __restrict__ out_h,
                         float alpha, float beta) {
    const int warp = (blockIdx.x * blockDim.x + threadIdx.x) >> 5;
    if (warp >= NN) return;
    const int node = warp;
    const int lane = threadIdx.x & 31;
    const int b  = lane >> 3;
    const int c8 = (lane & 7) * 8;

    const __half* base = in_h + (size_t)b * NN * CC + c8;

    float acc[8];
#pragma unroll
    for (int j = 0; j < 8; j++) acc[j] = 0.f;

    const int s0 = g_rowptr[node];
    const int s1 = g_rowptr[node + 1];

#pragma unroll 4
    for (int e = s0; e < s1; e++) {
        const int2 ev = g_edge[e];
        const float w = __int_as_float(ev.y);
        uint4 v = *(const uint4*)(base + (size_t)ev.x * CC);
        const __half2* hp = (const __half2*)&v;
#pragma unroll
        for (int j = 0; j < 4; j++) {
            float2 f = __half22float2(hp[j]);
            acc[2 * j]     += w * f.x;
            acc[2 * j + 1] += w * f.y;
        }
    }

    const size_t o = ((size_t)b * NN + node) * CC + c8;
    float r[8];
#pragma unroll
    for (int j = 0; j < 8; j++) r[j] = alpha * acc[j];
    if (beta != 0.f) {
        float4 a0 = *(const float4*)(addx + o);
        float4 a1 = *(const float4*)(addx + o + 4);
        r[0] += beta * a0.x; r[1] += beta * a0.y; r[2] += beta * a0.z; r[3] += beta * a0.w;
        r[4] += beta * a1.x; r[5] += beta * a1.y; r[6] += beta * a1.z; r[7] += beta * a1.w;
    }
    __half2 h[4];
    h[0] = __floats2half2_rn(r[0], r[1]);
    h[1] = __floats2half2_rn(r[2], r[3]);
    h[2] = __floats2half2_rn(r[4], r[5]);
    h[3] = __floats2half2_rn(r[6], r[7]);
    *(uint4*)(out_h + o) = *(uint4*)h;
}

// ---------------- launch 6: fused dense ------------------------------------
// out = relu([x|y1|y2] Wc + bc) Wl + bl
// 128 rows x 64 cols tile; 256 threads; warp -> 8 cols, lane -> 4 rows.
// Weights stored DUPLICATED in smem (b,b pairs) -> B loads are packed f32x2
// directly (no MOV dup). U staged in two 96-k halves to fit smem.
#define TR 128
#define KH 96          // k-half
#define PITCH 132

__global__ void __launch_bounds__(256, 1)
k_fused(const float* __restrict__ x,
        const float* __restrict__ Wc, const float* __restrict__ bc,
        const float* __restrict__ Wl, const float* __restrict__ bl,
        float* __restrict__ out) {
    extern __shared__ float sm[];
    float* UsH = sm;                        // [KH][PITCH]  (12672 f)
    float* Wc2 = sm + KH * PITCH;           // [192][128] dup (24576 f)
    float* Wl2 = Wc2 + 192 * 128;           // [64][128] dup  (8192 f)
    float* bcs = Wl2 + 64 * 128;            // [64]
    float* bls = bcs + CC;                  // [64]

    const int t = threadIdx.x;
    const int rowbase = blockIdx.x * TR;
    const int nrows = min(TR, NROWS - rowbase);

    // ---- stage duplicated weights ----
    for (int i = t; i < 192 * 16; i += 256) {           // 16 quads per Wc row
        const int k = i >> 4, q = i & 15;
        float4 v = ((const float4*)Wc)[k * 16 + q];
        float* dp = Wc2 + k * 128 + q * 8;
        *(float4*)(dp)     = make_float4(v.x, v.x, v.y, v.y);
        *(float4*)(dp + 4) = make_float4(v.z, v.z, v.w, v.w);
    }
    for (int i = t; i < 64 * 16; i += 256) {
        const int k = i >> 4, q = i & 15;
        float4 v = ((const float4*)Wl)[k * 16 + q];
        float* dp = Wl2 + k * 128 + q * 8;
        *(float4*)(dp)     = make_float4(v.x, v.x, v.y, v.y);
        *(float4*)(dp + 4) = make_float4(v.z, v.z, v.w, v.w);
    }
    if (t < CC) { bcs[t] = bc[t]; bls[t] = bl[t]; }

    const int w  = t >> 5;
    const int l  = t & 31;
    const int c0 = w * 8;
    const int r0 = l * 4;

    unsigned long long acc[2][8];
#pragma unroll
    for (int p = 0; p < 2; p++)
#pragma unroll
        for (int c = 0; c < 8; c++) acc[p][c] = 0ULL;

    // ---- phase 1 over two k-halves ----
    for (int h = 0; h < 2; h++) {
        if (h) __syncthreads();   // protect UsH from overwrite while h=0 in use
        // stage UsH: kk in [96h, 96h+96), k-major
        for (int i = t; i < TR * (KH / 4); i += 256) {
            const int row = i / (KH / 4);
            const int q   = i % (KH / 4);
            const int kkl = q * 4;                 // local k
            const int kkg = KH * h + kkl;          // global k
            const int seg = kkg >> 6;
            const int k4  = kkg & 63;
            float4 v = make_float4(0.f, 0.f, 0.f, 0.f);
            if (row < nrows) {
                const size_t off = (size_t)(rowbase + row) * CC + k4;
                if (seg == 0) {
                    v = *(const float4*)(x + off);
                } else {
                    const __half* hp = (seg == 1) ? g_y1h : g_y2h;
                    uint2 hv = *(const uint2*)(hp + off);
                    float2 f0 = __half22float2(*(const __half2*)&hv.x);
                    float2 f1 = __half22float2(*(const __half2*)&hv.y);
                    v = make_float4(f0.x, f0.y, f1.x, f1.y);
                }
            }
            UsH[(kkl + 0) * PITCH + row] = v.x;
            UsH[(kkl + 1) * PITCH + row] = v.y;
            UsH[(kkl + 2) * PITCH + row] = v.z;
            UsH[(kkl + 3) * PITCH + row] = v.w;
        }
        __syncthreads();

#pragma unroll 2
        for (int k = 0; k < KH; k++) {
            const ulonglong2 A = *(const ulonglong2*)(UsH + k * PITCH + r0);
            unsigned long long ap[2] = {A.x, A.y};
            const float* bp = Wc2 + (KH * h + k) * 128 + c0 * 2;
            const ulonglong2 B0 = *(const ulonglong2*)(bp);
            const ulonglong2 B1 = *(const ulonglong2*)(bp + 4);
            const ulonglong2 B2 = *(const ulonglong2*)(bp + 8);
            const ulonglong2 B3 = *(const ulonglong2*)(bp + 12);
            unsigned long long bb[8] = {B0.x, B0.y, B1.x, B1.y,
                                        B2.x, B2.y, B3.x, B3.y};
#pragma unroll
            for (int p = 0; p < 2; p++)
#pragma unroll
                for (int c = 0; c < 8; c++)
                    acc[p][c] = fma2(ap[p], bb[c], acc[p][c]);
        }
    }
    __syncthreads();

    // ---- epilogue 1: bias + relu -> Hs (k-major, reuses UsH) ----
#pragma unroll
    for (int p = 0; p < 2; p++) {
#pragma unroll
        for (int c = 0; c < 8; c++) {
            float lo, hi;
            unpk2(acc[p][c], lo, hi);
            const float b = bcs[c0 + c];
            lo = fmaxf(lo + b, 0.f);
            hi = fmaxf(hi + b, 0.f);
            UsH[(c0 + c) * PITCH + r0 + 2 * p]     = lo;
            UsH[(c0 + c) * PITCH + r0 + 2 * p + 1] = hi;
        }
    }
    __syncthreads();

    // ---- phase 2: out = h @ Wl ----
#pragma unroll
    for (int p = 0; p < 2; p++)
#pragma unroll
        for (int c = 0; c < 8; c++) acc[p][c] = 0ULL;

#pragma unroll 2
    for (int k = 0; k < CC; k++) {
        const ulonglong2 A = *(const ulonglong2*)(UsH + k * PITCH + r0);
        unsigned long long ap[2] = {A.x, A.y};
        const float* bp = Wl2 + k * 128 + c0 * 2;
        const ulonglong2 B0 = *(const ulonglong2*)(bp);
        const ulonglong2 B1 = *(const ulonglong2*)(bp + 4);
        const ulonglong2 B2 = *(const ulonglong2*)(bp + 8);
        const ulonglong2 B3 = *(const ulonglong2*)(bp + 12);
        unsigned long long bb[8] = {B0.x, B0.y, B1.x, B1.y,
                                    B2.x, B2.y, B3.x, B3.y};
#pragma unroll
        for (int p = 0; p < 2; p++)
#pragma unroll
            for (int c = 0; c < 8; c++)
                acc[p][c] = fma2(ap[p], bb[c], acc[p][c]);
    }

    // ---- epilogue 2: bias + store ----
    float res[4][8];
#pragma unroll
    for (int p = 0; p < 2; p++)
#pragma unroll
        for (int c = 0; c < 8; c++) {
            float lo, hi;
            unpk2(acc[p][c], lo, hi);
            const float b = bls[c0 + c];
            res[2 * p][c]     = lo + b;
            res[2 * p + 1][c] = hi + b;
        }
#pragma unroll
    for (int j = 0; j < 4; j++) {
        const int r = r0 + j;
        if (r < nrows) {
            float* op = out + (size_t)(rowbase + r) * CC + c0;
            *(float4*)(op)     = make_float4(res[j][0], res[j][1], res[j][2], res[j][3]);
            *(float4*)(op + 4) = make_float4(res[j][4], res[j][5], res[j][6], res[j][7]);
        }
    }
}

// ---------------- launch ----------------
extern "C" void kernel_launch(void* const* d_in, const int* in_sizes, int n_in,
                              void* d_out, int out_size) {
    const float* x   = (const float*)d_in[0];
    const int*   src = (const int*)d_in[1];
    const int*   dst = (const int*)d_in[2];
    const float* Wc  = (const float*)d_in[3];
    const float* bc  = (const float*)d_in[4];
    const float* Wl  = (const float*)d_in[5];
    const float* bl  = (const float*)d_in[6];
    float* out = (float*)d_out;

    static bool attr_set = false;
    const int fused_smem = (KH * PITCH + 192 * 128 + 64 * 128 + 2 * CC) * 4;
    if (!attr_set) {
        cudaFuncSetAttribute(k_fused, cudaFuncAttributeMaxDynamicSharedMemorySize,
                             fused_smem);
        attr_set = true;
    }

    __half *xh, *y1h, *y2h;
    cudaGetSymbolAddress((void**)&xh,  g_xh);
    cudaGetSymbolAddress((void**)&y1h, g_y1h);
    cudaGetSymbolAddress((void**)&y2h, g_y2h);

    // 1: degrees (g_deg starts zeroed: static init / re-zeroed by k_fill3)
    k_degree<<<(EE + 255) / 256, 256>>>(dst);
    // 2: rowptr + norm (self-contained scan)
    k_emit2<<<SNB, SBS>>>();
    // 3: edge fill + x->fp16 + re-zero deg
    k_fill3<<<(NROWS * CC / 8 + 255) / 256, 256>>>(src, dst, x);
    // 4: y1h = fp16(-(A xh))               <-- ncu captures this launch
    k_spmm_h<<<(NN + 7) / 8, 256>>>(xh, nullptr, y1h, -1.f, 0.f);
    // 5: y2h = fp16(-2 (A y1h) - x)
    k_spmm_h<<<(NN + 7) / 8, 256>>>(y1h, x, y2h, -2.f, -1.f);
    // 6: fused dense
    const int nblk = (NROWS + TR - 1) / TR;
    k_fused<<<nblk, 256, fused_smem>>>(x, Wc, bc, Wl, bl, out);
}

// round 6
// speedup vs baseline: 2.1423x; 1.6541x over previous
#include <cuda_runtime.h>
#include <cuda_fp16.h>
#include <cstdint>

// Problem constants
#define NN 50000
#define EE 800000
#define BB 4
#define CC 64
#define NROWS (BB*NN)
#define SBS 256
#define SNB ((NN + SBS - 1) / SBS)

// ---------------- scratch (device globals) ----------------
__device__ int    g_deg[NN];          // zero at load; re-zeroed by k_fill3 each run
__device__ float  g_norm[NN];
__device__ int    g_rowptr[NN + 1];
__device__ int    g_fill[NN];
__device__ int2   g_edge[EE];         // (src, weight-bits)
__device__ __half g_xh[(size_t)NROWS * CC];
__device__ __half g_y1h[(size_t)NROWS * CC];
__device__ __half g_y2h[(size_t)NROWS * CC];

// ---------------- tf32 / mma helpers ----------------
__device__ __forceinline__ unsigned tf32b(float f) {
    unsigned r; asm("cvt.rna.tf32.f32 %0, %1;" : "=r"(r) : "f"(f)); return r;
}
__device__ __forceinline__ void mma8(float* c,
                                     unsigned a0, unsigned a1, unsigned a2, unsigned a3,
                                     unsigned b0, unsigned b1) {
    asm volatile("mma.sync.aligned.m16n8k8.row.col.f32.tf32.tf32.f32 "
                 "{%0,%1,%2,%3}, {%4,%5,%6,%7}, {%8,%9}, {%0,%1,%2,%3};"
                 : "+f"(c[0]), "+f"(c[1]), "+f"(c[2]), "+f"(c[3])
                 : "r"(a0), "r"(a1), "r"(a2), "r"(a3), "r"(b0), "r"(b1));
}

// ---------------- launch 1: degree ----------------
__global__ void k_degree(const int* __restrict__ dst) {
    int e = blockIdx.x * blockDim.x + threadIdx.x;
    if (e < EE) atomicAdd(&g_deg[dst[e]], 1);
}

// ---------------- launch 2: scan + emit ----------------
__global__ void k_emit2() {
    __shared__ int sh[SBS];
    const int t = threadIdx.x;
    const int i = blockIdx.x * SBS + t;

    const int lim = blockIdx.x * SBS;      // multiple of 256 -> int4-aligned
    int s = 0;
    for (int j = t * 4; j < lim; j += SBS * 4) {
        int4 v = *(const int4*)(g_deg + j);
        s += v.x + v.y + v.z + v.w;
    }
    sh[t] = s;
    __syncthreads();
    for (int off = SBS / 2; off > 0; off >>= 1) {
        if (t < off) sh[t] += sh[t + off];
        __syncthreads();
    }
    const int boff = sh[0];
    __syncthreads();

    const int d = (i < NN) ? g_deg[i] : 0;
    sh[t] = d;
    __syncthreads();
    for (int off = 1; off < SBS; off <<= 1) {
        int u = (t >= off) ? sh[t - off] : 0;
        __syncthreads();
        sh[t] += u;
        __syncthreads();
    }
    if (i < NN) {
        const int rp = boff + sh[t] - d;
        g_rowptr[i] = rp;
        g_fill[i]   = rp;
        g_norm[i]   = rsqrtf((float)(d < 1 ? 1 : d));
    }
    if (i == 0) g_rowptr[NN] = EE;
}

// ---------------- launch 3: fill edges + x->fp16 + re-zero deg ----------------
__global__ void k_fill3(const int* __restrict__ src, const int* __restrict__ dst,
                        const float* __restrict__ x) {
    const int tid = blockIdx.x * blockDim.x + threadIdx.x;

    const size_t i8 = (size_t)tid * 8;
    if (i8 < (size_t)NROWS * CC) {
        float4 a = *(const float4*)(x + i8);
        float4 b = *(const float4*)(x + i8 + 4);
        __half2 h[4];
        h[0] = __floats2half2_rn(a.x, a.y);
        h[1] = __floats2half2_rn(a.z, a.w);
        h[2] = __floats2half2_rn(b.x, b.y);
        h[3] = __floats2half2_rn(b.z, b.w);
        *(uint4*)(g_xh + i8) = *(uint4*)h;
    }

    if (tid < EE) {
        const int d = dst[tid];
        const int s = src[tid];
        const int p = atomicAdd(&g_fill[d], 1);
        g_edge[p] = make_int2(s, __float_as_int(g_norm[s] * g_norm[d]));
    }

    if (tid < NN / 4) ((int4*)g_deg)[tid] = make_int4(0, 0, 0, 0);
}

// ---------------- launches 4,5: SPMM (fp16 gather, fp32 acc, fp16 out) -------
__global__ void k_spmm_h(const __half* __restrict__ in_h,
                         const float* __restrict__ addx,
                         __half* __restrict__ out_h,
                         float alpha, float beta) {
    const int warp = (blockIdx.x * blockDim.x + threadIdx.x) >> 5;
    if (warp >= NN) return;
    const int node = warp;
    const int lane = threadIdx.x & 31;
    const int b  = lane >> 3;
    const int c8 = (lane & 7) * 8;

    const __half* base = in_h + (size_t)b * NN * CC + c8;

    float acc[8];
#pragma unroll
    for (int j = 0; j < 8; j++) acc[j] = 0.f;

    const int s0 = g_rowptr[node];
    const int s1 = g_rowptr[node + 1];

#pragma unroll 4
    for (int e = s0; e < s1; e++) {
        const int2 ev = g_edge[e];
        const float w = __int_as_float(ev.y);
        uint4 v = *(const uint4*)(base + (size_t)ev.x * CC);
        const __half2* hp = (const __half2*)&v;
#pragma unroll
        for (int j = 0; j < 4; j++) {
            float2 f = __half22float2(hp[j]);
            acc[2 * j]     += w * f.x;
            acc[2 * j + 1] += w * f.y;
        }
    }

    const size_t o = ((size_t)b * NN + node) * CC + c8;
    float r[8];
#pragma unroll
    for (int j = 0; j < 8; j++) r[j] = alpha * acc[j];
    if (beta != 0.f) {
        float4 a0 = *(const float4*)(addx + o);
        float4 a1 = *(const float4*)(addx + o + 4);
        r[0] += beta * a0.x; r[1] += beta * a0.y; r[2] += beta * a0.z; r[3] += beta * a0.w;
        r[4] += beta * a1.x; r[5] += beta * a1.y; r[6] += beta * a1.z; r[7] += beta * a1.w;
    }
    __half2 h[4];
    h[0] = __floats2half2_rn(r[0], r[1]);
    h[1] = __floats2half2_rn(r[2], r[3]);
    h[2] = __floats2half2_rn(r[4], r[5]);
    h[3] = __floats2half2_rn(r[6], r[7]);
    *(uint4*)(out_h + o) = *(uint4*)h;
}

// ---------------- launch 6: fused dense via tf32 mma.sync --------------------
// out = relu([x|y1|y2] Wc + bc) Wl + bl
// CTA: 128 rows x 64 cols, 256 threads (8 warps). Warp tile 32x32:
//   mtile = w>>1 (rows 32*mtile), nt2 = w&1 (cols 32*nt2)
// smem holds operands pre-converted to tf32 bits, pre-permuted to exact
// m16n8k8 fragment layout -> main loop = LDS.128 + MMA only.
#define TR 128
#define NKT1 24          // phase-1 k-steps (K=192)
#define NKT2 8           // phase-2 k-steps (K=64)
#define BSTRIDE 20       // Bf row stride in floats (16 data + 4 pad, conflict-free)
#define HPITCH 68        // Hs row pitch in floats

__global__ void __launch_bounds__(256, 1)
k_fused(const float* __restrict__ x,
        const float* __restrict__ Wc, const float* __restrict__ bc,
        const float* __restrict__ Wl, const float* __restrict__ bl,
        float* __restrict__ out) {
    extern __shared__ float sm[];
    float* Af  = sm;                         // 24*8*32*4 = 24576 f (phase1 A frags)
    float* Bf  = sm + NKT1 * 8 * 32 * 4;     // 24*32*20 = 15360 f (phase1 B frags)
    float* Bl2 = Bf + NKT1 * 32 * BSTRIDE;   //  8*32*20 =  5120 f (phase2 B frags)
    float* bcs = Bl2 + NKT2 * 32 * BSTRIDE;  // 64
    float* bls = bcs + 64;                   // 64
    float* Hs  = Af;                         // overlay: 128*68 = 8704 f (phase2 A)

    const int t    = threadIdx.x;
    const int lane = t & 31;
    const int w    = t >> 5;
    const int rowbase = blockIdx.x * TR;
    const int nrows = min(TR, NROWS - rowbase);

    // ---- stage Bf (Wc: [192][64], B[k][n]) into fragment layout ----
    // slot s = (kt, lane'): 16 values v[nt*2+j] = tf32(Wc[(8kt+tid'+4j)*64 + 8nt+g'])
    for (int s = t; s < NKT1 * 32; s += 256) {
        const int kt = s >> 5, ln = s & 31;
        const int gg = ln >> 2, tt = ln & 3;
        unsigned v[16];
#pragma unroll
        for (int nt = 0; nt < 8; nt++)
#pragma unroll
            for (int j = 0; j < 2; j++)
                v[nt * 2 + j] = tf32b(Wc[(kt * 8 + tt + 4 * j) * 64 + nt * 8 + gg]);
        uint4* dp = (uint4*)(Bf + s * BSTRIDE);
        dp[0] = make_uint4(v[0],  v[1],  v[2],  v[3]);
        dp[1] = make_uint4(v[4],  v[5],  v[6],  v[7]);
        dp[2] = make_uint4(v[8],  v[9],  v[10], v[11]);
        dp[3] = make_uint4(v[12], v[13], v[14], v[15]);
    }
    // ---- stage Bl2 (Wl: [64][64]) ----
    for (int s = t; s < NKT2 * 32; s += 256) {
        const int kt = s >> 5, ln = s & 31;
        const int gg = ln >> 2, tt = ln & 3;
        unsigned v[16];
#pragma unroll
        for (int nt = 0; nt < 8; nt++)
#pragma unroll
            for (int j = 0; j < 2; j++)
                v[nt * 2 + j] = tf32b(Wl[(kt * 8 + tt + 4 * j) * 64 + nt * 8 + gg]);
        uint4* dp = (uint4*)(Bl2 + s * BSTRIDE);
        dp[0] = make_uint4(v[0],  v[1],  v[2],  v[3]);
        dp[1] = make_uint4(v[4],  v[5],  v[6],  v[7]);
        dp[2] = make_uint4(v[8],  v[9],  v[10], v[11]);
        dp[3] = make_uint4(v[12], v[13], v[14], v[15]);
    }
    if (t < 64) { bcs[t] = bc[t]; bls[t] = bl[t]; }

    // ---- stage Af: U = [x | y1h | y2h] rows [rowbase, rowbase+128) ----
    // slot idx = (kt, rt, lane'): {a0,a1,a2,a3} =
    //   U[16rt+g'][8kt+tid'], U[16rt+g'+8][...], U[16rt+g'][8kt+tid'+4], U[+8][+4]
    for (int idx = t; idx < NKT1 * 8 * 32; idx += 256) {
        const int kt  = idx >> 8;
        const int rem = idx & 255;
        const int rt  = rem >> 5;
        const int ln  = rem & 31;
        const int gg = ln >> 2, tt = ln & 3;
        const int r0 = rt * 16 + gg;          // local row
        const int c0 = kt * 8 + tt;           // global k col
        float a0 = 0.f, a1 = 0.f, a2 = 0.f, a3 = 0.f;
        if (kt < 8) {
            const float* p = x + (size_t)rowbase * CC;
            if (r0 < nrows)     { a0 = p[(size_t)r0 * CC + c0];
                                  a2 = p[(size_t)r0 * CC + c0 + 4]; }
            if (r0 + 8 < nrows) { a1 = p[(size_t)(r0 + 8) * CC + c0];
                                  a3 = p[(size_t)(r0 + 8) * CC + c0 + 4]; }
        } else {
            const __half* p = ((kt < 16) ? g_y1h : g_y2h) + (size_t)rowbase * CC;
            const int cc = c0 - ((kt < 16) ? 64 : 128);
            if (r0 < nrows)     { a0 = __half2float(p[(size_t)r0 * CC + cc]);
                                  a2 = __half2float(p[(size_t)r0 * CC + cc + 4]); }
            if (r0 + 8 < nrows) { a1 = __half2float(p[(size_t)(r0 + 8) * CC + cc]);
                                  a3 = __half2float(p[(size_t)(r0 + 8) * CC + cc + 4]); }
        }
        *(uint4*)(Af + idx * 4) = make_uint4(tf32b(a0), tf32b(a1), tf32b(a2), tf32b(a3));
    }
    __syncthreads();

    const int mtile = w >> 1;     // 0..3
    const int nt2   = w & 1;      // 0..1
    const int g = lane >> 2, tid = lane & 3;

    // ---- phase 1: h = U @ Wc ----
    float c1[2][4][4];
#pragma unroll
    for (int m = 0; m < 2; m++)
#pragma unroll
        for (int n = 0; n < 4; n++)
#pragma unroll
            for (int q = 0; q < 4; q++) c1[m][n][q] = 0.f;

#pragma unroll 4
    for (int kt = 0; kt < NKT1; kt++) {
        const uint4 A0 = *(const uint4*)(Af + ((kt * 8 + mtile * 2    ) * 32 + lane) * 4);
        const uint4 A1 = *(const uint4*)(Af + ((kt * 8 + mtile * 2 + 1) * 32 + lane) * 4);
        const float* bp = Bf + (kt * 32 + lane) * BSTRIDE + nt2 * 8;
        const uint4 B0 = *(const uint4*)(bp);
        const uint4 B1 = *(const uint4*)(bp + 4);
        mma8(c1[0][0], A0.x, A0.y, A0.z, A0.w, B0.x, B0.y);
        mma8(c1[0][1], A0.x, A0.y, A0.z, A0.w, B0.z, B0.w);
        mma8(c1[0][2], A0.x, A0.y, A0.z, A0.w, B1.x, B1.y);
        mma8(c1[0][3], A0.x, A0.y, A0.z, A0.w, B1.z, B1.w);
        mma8(c1[1][0], A1.x, A1.y, A1.z, A1.w, B0.x, B0.y);
        mma8(c1[1][1], A1.x, A1.y, A1.z, A1.w, B0.z, B0.w);
        mma8(c1[1][2], A1.x, A1.y, A1.z, A1.w, B1.x, B1.y);
        mma8(c1[1][3], A1.x, A1.y, A1.z, A1.w, B1.z, B1.w);
    }
    __syncthreads();   // all Af reads complete before Hs overlay

    // ---- epilogue 1: bias + relu -> tf32 bits into Hs ----
#pragma unroll
    for (int m = 0; m < 2; m++) {
        const int R = mtile * 32 + m * 16 + g;
#pragma unroll
        for (int n = 0; n < 4; n++) {
            const int Cl = nt2 * 32 + n * 8 + 2 * tid;
            const float b0 = bcs[Cl], b1 = bcs[Cl + 1];
            const float v0 = fmaxf(c1[m][n][0] + b0, 0.f);
            const float v1 = fmaxf(c1[m][n][1] + b1, 0.f);
            const float v2 = fmaxf(c1[m][n][2] + b0, 0.f);
            const float v3 = fmaxf(c1[m][n][3] + b1, 0.f);
            *(float2*)(Hs + R * HPITCH + Cl) =
                make_float2(__uint_as_float(tf32b(v0)), __uint_as_float(tf32b(v1)));
            *(float2*)(Hs + (R + 8) * HPITCH + Cl) =
                make_float2(__uint_as_float(tf32b(v2)), __uint_as_float(tf32b(v3)));
        }
    }
    __syncthreads();

    // ---- phase 2: out = h @ Wl ----
    float c2[2][4][4];
#pragma unroll
    for (int m = 0; m < 2; m++)
#pragma unroll
        for (int n = 0; n < 4; n++)
#pragma unroll
            for (int q = 0; q < 4; q++) c2[m][n][q] = 0.f;

#pragma unroll
    for (int kt = 0; kt < NKT2; kt++) {
        unsigned a[2][4];
#pragma unroll
        for (int m = 0; m < 2; m++) {
            const int Rb = mtile * 32 + m * 16;
            a[m][0] = __float_as_uint(Hs[(Rb + g    ) * HPITCH + kt * 8 + tid    ]);
            a[m][1] = __float_as_uint(Hs[(Rb + g + 8) * HPITCH + kt * 8 + tid    ]);
            a[m][2] = __float_as_uint(Hs[(Rb + g    ) * HPITCH + kt * 8 + tid + 4]);
            a[m][3] = __float_as_uint(Hs[(Rb + g + 8) * HPITCH + kt * 8 + tid + 4]);
        }
        const float* bp = Bl2 + (kt * 32 + lane) * BSTRIDE + nt2 * 8;
        const uint4 B0 = *(const uint4*)(bp);
        const uint4 B1 = *(const uint4*)(bp + 4);
#pragma unroll
        for (int m = 0; m < 2; m++) {
            mma8(c2[m][0], a[m][0], a[m][1], a[m][2], a[m][3], B0.x, B0.y);
            mma8(c2[m][1], a[m][0], a[m][1], a[m][2], a[m][3], B0.z, B0.w);
            mma8(c2[m][2], a[m][0], a[m][1], a[m][2], a[m][3], B1.x, B1.y);
            mma8(c2[m][3], a[m][0], a[m][1], a[m][2], a[m][3], B1.z, B1.w);
        }
    }

    // ---- epilogue 2: bias + store ----
#pragma unroll
    for (int m = 0; m < 2; m++) {
        const int Rl = mtile * 32 + m * 16 + g;
#pragma unroll
        for (int n = 0; n < 4; n++) {
            const int Cl = nt2 * 32 + n * 8 + 2 * tid;
            const float b0 = bls[Cl], b1 = bls[Cl + 1];
            if (Rl < nrows)
                *(float2*)(out + (size_t)(rowbase + Rl) * CC + Cl) =
                    make_float2(c2[m][n][0] + b0, c2[m][n][1] + b1);
            if (Rl + 8 < nrows)
                *(float2*)(out + (size_t)(rowbase + Rl + 8) * CC + Cl) =
                    make_float2(c2[m][n][2] + b0, c2[m][n][3] + b1);
        }
    }
}

// ---------------- launch ----------------
extern "C" void kernel_launch(void* const* d_in, const int* in_sizes, int n_in,
                              void* d_out, int out_size) {
    const float* x   = (const float*)d_in[0];
    const int*   src = (const int*)d_in[1];
    const int*   dst = (const int*)d_in[2];
    const float* Wc  = (const float*)d_in[3];
    const float* bc  = (const float*)d_in[4];
    const float* Wl  = (const float*)d_in[5];
    const float* bl  = (const float*)d_in[6];
    float* out = (float*)d_out;

    const int fused_smem = (NKT1 * 8 * 32 * 4 + NKT1 * 32 * BSTRIDE +
                            NKT2 * 32 * BSTRIDE + 128) * 4;
    static bool attr_set = false;
    if (!attr_set) {
        cudaFuncSetAttribute(k_fused, cudaFuncAttributeMaxDynamicSharedMemorySize,
                             fused_smem);
        attr_set = true;
    }

    __half *xh, *y1h, *y2h;
    cudaGetSymbolAddress((void**)&xh,  g_xh);
    cudaGetSymbolAddress((void**)&y1h, g_y1h);
    cudaGetSymbolAddress((void**)&y2h, g_y2h);

    // 1: degrees (g_deg zeroed at load / re-zeroed by k_fill3 each run)
    k_degree<<<(EE + 255) / 256, 256>>>(dst);
    // 2: rowptr + norm
    k_emit2<<<SNB, SBS>>>();
    // 3: edge fill + x->fp16 + re-zero deg
    k_fill3<<<(NROWS * CC / 8 + 255) / 256, 256>>>(src, dst, x);
    // 4: y1h = fp16(-(A xh))
    k_spmm_h<<<(NN + 7) / 8, 256>>>(xh, nullptr, y1h, -1.f, 0.f);
    // 5: y2h = fp16(-2 (A y1h) - x)
    k_spmm_h<<<(NN + 7) / 8, 256>>>(y1h, x, y2h, -2.f, -1.f);
    // 6: fused dense (tf32 tensor cores)
    const int nblk = (NROWS + TR - 1) / TR;
    k_fused<<<nblk, 256, fused_smem>>>(x, Wc, bc, Wl, bl, out);
}